// round 2
// baseline (speedup 1.0000x reference)
#include <cuda_runtime.h>
#include <cuda_bf16.h>
#include <math_constants.h>

// Focal loss: input [N, C=1000] fp32 logits, target [N] (int32 on device).
// loss_i = -(1 - p_t)^2 * w_t * logp_t,  w_t = (t>0 ? 0.25 : 0.75)
// output = mean(loss)
//
// One warp per row: 250 float4 per row, each lane front-loads up to 8
// independent float4 (MLP=8), register two-phase softmax, warp shuffle
// reductions, lane 0 gathers x[row, t] (L1-hot) and forms the loss.
// 8 warp partials -> shared -> one atomicAdd per block.

#define FL_C   1000
#define FL_NV  250      // float4s per row
#define FL_WPB 8        // warps per block
#define FL_TPB (FL_WPB * 32)

__global__ __launch_bounds__(FL_TPB)
void focal_loss_kernel(const float* __restrict__ x,
                       const int* __restrict__ tgt,
                       float* __restrict__ out,
                       int n_rows, float inv_n)
{
    const int lane = threadIdx.x & 31;
    const int wid  = threadIdx.x >> 5;
    const int row  = blockIdx.x * FL_WPB + wid;

    float partial = 0.0f;

    if (row < n_rows) {
        const float4* rp = reinterpret_cast<const float4*>(x + (size_t)row * FL_C);

        // Batched front loads: 8 independent float4 per lane (lanes 26..31 do 7).
        float4 v[8];
#pragma unroll
        for (int k = 0; k < 8; k++) {
            int i = lane + k * 32;
            if (i < FL_NV) {
                v[k] = rp[i];
            } else {
                v[k] = make_float4(-CUDART_INF_F, -CUDART_INF_F,
                                   -CUDART_INF_F, -CUDART_INF_F);
            }
        }

        // Row max (register phase then warp shuffle).
        float m = -CUDART_INF_F;
#pragma unroll
        for (int k = 0; k < 8; k++) {
            m = fmaxf(m, fmaxf(fmaxf(v[k].x, v[k].y), fmaxf(v[k].z, v[k].w)));
        }
#pragma unroll
        for (int o = 16; o > 0; o >>= 1)
            m = fmaxf(m, __shfl_xor_sync(0xffffffffu, m, o));

        // Sum of exp(x - m). __expf(-inf) == 0, so padding lanes are harmless.
        float s = 0.0f;
#pragma unroll
        for (int k = 0; k < 8; k++) {
            s += __expf(v[k].x - m) + __expf(v[k].y - m)
               + __expf(v[k].z - m) + __expf(v[k].w - m);
        }
#pragma unroll
        for (int o = 16; o > 0; o >>= 1)
            s += __shfl_xor_sync(0xffffffffu, s, o);

        if (lane == 0) {
            int t = tgt[row];
            int tc = t < 0 ? 0 : (t >= FL_C ? FL_C - 1 : t);   // safety clamp
            float xt = __ldg(x + (size_t)row * FL_C + (size_t)tc);  // hot in L1/L2
            float logpt = xt - m - __logf(s);
            float pt = __expf(logpt);
            float w  = (t > 0) ? 0.25f : 0.75f;
            float om = 1.0f - pt;
            partial = -(om * om) * (w * logpt) * inv_n;
        }
    }

    // Block reduce 8 warp partials, single atomic per block.
    __shared__ float smem[FL_WPB];
    if (lane == 0) smem[wid] = partial;
    __syncthreads();
    if (threadIdx.x == 0) {
        float b = 0.0f;
#pragma unroll
        for (int i = 0; i < FL_WPB; i++) b += smem[i];
        atomicAdd(out, b);
    }
}

extern "C" void kernel_launch(void* const* d_in, const int* in_sizes, int n_in,
                              void* d_out, int out_size)
{
    const float* x   = (const float*)d_in[0];
    const int*   tgt = (const int*)d_in[1];
    float*       out = (float*)d_out;

    const int n_rows = in_sizes[1];          // 262144 targets
    const float inv_n = 1.0f / (float)n_rows;

    // Output is poisoned to 0xAA; zero it (memset nodes are graph-capturable).
    cudaMemsetAsync(d_out, 0, (size_t)out_size * sizeof(float), 0);

    const int blocks = (n_rows + FL_WPB - 1) / FL_WPB;
    focal_loss_kernel<<<blocks, FL_TPB>>>(x, tgt, out, n_rows, inv_n);
}

// round 3
// speedup vs baseline: 1.0158x; 1.0158x over previous
#include <cuda_runtime.h>
#include <cuda_bf16.h>
#include <math_constants.h>

// Focal loss: input [N, C=1000] fp32 logits, target [N] int32.
// loss_i = -(1 - p_t)^2 * w_t * logp_t,  w_t = (t>0 ? 0.25 : 0.75)
// output = mean(loss)
//
// One warp per row, 8 batched float4 loads per lane (MLP=8, __ldcs streaming),
// register two-phase softmax, shuffle reductions. x[row,t] is extracted from
// the registers already holding it (no gather re-load). Per-block partial is
// atomically accumulated into a __device__ scratch; the LAST block (atomic
// ticket) writes the final mean to d_out and resets scratch -> single kernel
// node, no memset, graph-replay deterministic.

#define FL_C   1000
#define FL_NV  250      // float4s per row
#define FL_WPB 8        // warps per block
#define FL_TPB (FL_WPB * 32)

__device__ float    g_fl_scratch = 0.0f;
__device__ unsigned g_fl_ticket  = 0u;

__global__ __launch_bounds__(FL_TPB)
void focal_loss_kernel(const float* __restrict__ x,
                       const int* __restrict__ tgt,
                       float* __restrict__ out,
                       int n_rows, float inv_n)
{
    const int lane = threadIdx.x & 31;
    const int wid  = threadIdx.x >> 5;
    const int row  = blockIdx.x * FL_WPB + wid;

    float partial = 0.0f;

    if (row < n_rows) {
        const float4* rp = reinterpret_cast<const float4*>(x + (size_t)row * FL_C);
        const int t = tgt[row];                 // broadcast load, one sector/warp

        // Batched streaming loads: 8 independent float4 per lane (lanes 26..31 do 7).
        float4 v[8];
#pragma unroll
        for (int k = 0; k < 8; k++) {
            int i = lane + k * 32;
            if (i < FL_NV) {
                v[k] = __ldcs(rp + i);          // evict-first: pure streaming
            } else {
                v[k] = make_float4(-CUDART_INF_F, -CUDART_INF_F,
                                   -CUDART_INF_F, -CUDART_INF_F);
            }
        }

        // Row max.
        float m = -CUDART_INF_F;
#pragma unroll
        for (int k = 0; k < 8; k++)
            m = fmaxf(m, fmaxf(fmaxf(v[k].x, v[k].y), fmaxf(v[k].z, v[k].w)));
#pragma unroll
        for (int o = 16; o > 0; o >>= 1)
            m = fmaxf(m, __shfl_xor_sync(0xffffffffu, m, o));

        // Sum of exp(x - m). __expf(-inf) == 0, padding lanes harmless.
        float s = 0.0f;
#pragma unroll
        for (int k = 0; k < 8; k++) {
            s += __expf(v[k].x - m) + __expf(v[k].y - m)
               + __expf(v[k].z - m) + __expf(v[k].w - m);
        }
#pragma unroll
        for (int o = 16; o > 0; o >>= 1)
            s += __shfl_xor_sync(0xffffffffu, s, o);

        // Extract x[row, t] from registers: owner lane = (t>>2)&31,
        // register = t>>7, component = t&3. Unrolled predicated select
        // avoids dynamic register indexing (no local-mem spill).
        const int q     = t >> 2;
        const int owner = q & 31;
        const int kreg  = q >> 5;
        const int comp  = t & 3;
        float xt_local = 0.0f;
#pragma unroll
        for (int k = 0; k < 8; k++) {
            float4 c = v[k];
            float cc = (comp & 2) ? ((comp & 1) ? c.w : c.z)
                                  : ((comp & 1) ? c.y : c.x);
            if (k == kreg) xt_local = cc;
        }
        const float xt = __shfl_sync(0xffffffffu, xt_local, owner);

        if (lane == 0) {
            float logpt = xt - m - __logf(s);
            float pt = __expf(logpt);
            float w  = (t > 0) ? 0.25f : 0.75f;
            float om = 1.0f - pt;
            partial = -(om * om) * (w * logpt) * inv_n;
        }
    }

    // Block reduce 8 warp partials.
    __shared__ float smem[FL_WPB];
    if (lane == 0) smem[wid] = partial;
    __syncthreads();

    if (threadIdx.x == 0) {
        float b = 0.0f;
#pragma unroll
        for (int i = 0; i < FL_WPB; i++) b += smem[i];

        atomicAdd(&g_fl_scratch, b);
        __threadfence();
        unsigned ticket = atomicAdd(&g_fl_ticket, 1u);
        if (ticket == (unsigned)gridDim.x - 1u) {
            // Last block: all other blocks' adds are visible (their fences
            // ordered scratch-add before ticket-add).
            out[0] = g_fl_scratch;
            g_fl_scratch = 0.0f;    // reset for next graph replay
            g_fl_ticket  = 0u;
        }
    }
}

extern "C" void kernel_launch(void* const* d_in, const int* in_sizes, int n_in,
                              void* d_out, int out_size)
{
    const float* x   = (const float*)d_in[0];
    const int*   tgt = (const int*)d_in[1];
    float*       out = (float*)d_out;

    const int n_rows = in_sizes[1];          // 262144 targets
    const float inv_n = 1.0f / (float)n_rows;

    const int blocks = (n_rows + FL_WPB - 1) / FL_WPB;
    focal_loss_kernel<<<blocks, FL_TPB>>>(x, tgt, out, n_rows, inv_n);
}

// round 4
// speedup vs baseline: 1.0171x; 1.0013x over previous
#include <cuda_runtime.h>
#include <cuda_bf16.h>
#include <math_constants.h>

// Focal loss: input [N, C=1000] fp32 logits, target [N] int32.
// loss_i = -(1 - p_t)^2 * w_t * logp_t,  w_t = (t>0 ? 0.25 : 0.75)
// output = mean(loss)
//
// One warp per row, 8 batched float4 loads per lane (MLP=8, DEFAULT cache
// policy -- __ldcs measurably cost ~2% DRAM throughput in R3), register
// two-phase softmax, shuffle reductions. x[row,t] extracted from the
// registers already holding it. Per-block partial atomically accumulated
// into __device__ scratch; last block (atomic ticket) writes the mean to
// d_out and resets scratch -> single kernel node, graph-replay safe.

#define FL_C   1000
#define FL_NV  250      // float4s per row
#define FL_WPB 8        // warps per block
#define FL_TPB (FL_WPB * 32)

__device__ float    g_fl_scratch = 0.0f;
__device__ unsigned g_fl_ticket  = 0u;

__global__ __launch_bounds__(FL_TPB)
void focal_loss_kernel(const float* __restrict__ x,
                       const int* __restrict__ tgt,
                       float* __restrict__ out,
                       int n_rows, float inv_n)
{
    const int lane = threadIdx.x & 31;
    const int wid  = threadIdx.x >> 5;
    const int row  = blockIdx.x * FL_WPB + wid;

    float partial = 0.0f;

    if (row < n_rows) {
        const float4* rp = reinterpret_cast<const float4*>(x + (size_t)row * FL_C);
        const int t = tgt[row];                 // broadcast load, one sector/warp

        // Batched loads, default cache policy: 8 independent float4 per lane.
        float4 v[8];
#pragma unroll
        for (int k = 0; k < 8; k++) {
            int i = lane + k * 32;
            if (i < FL_NV) {
                v[k] = __ldg(rp + i);
            } else {
                v[k] = make_float4(-CUDART_INF_F, -CUDART_INF_F,
                                   -CUDART_INF_F, -CUDART_INF_F);
            }
        }

        // Row max.
        float m = -CUDART_INF_F;
#pragma unroll
        for (int k = 0; k < 8; k++)
            m = fmaxf(m, fmaxf(fmaxf(v[k].x, v[k].y), fmaxf(v[k].z, v[k].w)));
#pragma unroll
        for (int o = 16; o > 0; o >>= 1)
            m = fmaxf(m, __shfl_xor_sync(0xffffffffu, m, o));

        // Sum of exp(x - m). __expf(-inf) == 0, padding lanes harmless.
        float s = 0.0f;
#pragma unroll
        for (int k = 0; k < 8; k++) {
            s += __expf(v[k].x - m) + __expf(v[k].y - m)
               + __expf(v[k].z - m) + __expf(v[k].w - m);
        }
#pragma unroll
        for (int o = 16; o > 0; o >>= 1)
            s += __shfl_xor_sync(0xffffffffu, s, o);

        // Extract x[row, t] from registers: owner lane = (t>>2)&31,
        // register = t>>7, component = t&3. Unrolled predicated select
        // avoids dynamic register indexing (no local-mem spill).
        const int q     = t >> 2;
        const int owner = q & 31;
        const int kreg  = q >> 5;
        const int comp  = t & 3;
        float xt_local = 0.0f;
#pragma unroll
        for (int k = 0; k < 8; k++) {
            float4 c = v[k];
            float cc = (comp & 2) ? ((comp & 1) ? c.w : c.z)
                                  : ((comp & 1) ? c.y : c.x);
            if (k == kreg) xt_local = cc;
        }
        const float xt = __shfl_sync(0xffffffffu, xt_local, owner);

        if (lane == 0) {
            float logpt = xt - m - __logf(s);
            float pt = __expf(logpt);
            float w  = (t > 0) ? 0.25f : 0.75f;
            float om = 1.0f - pt;
            partial = -(om * om) * (w * logpt) * inv_n;
        }
    }

    // Block reduce 8 warp partials.
    __shared__ float smem[FL_WPB];
    if (lane == 0) smem[wid] = partial;
    __syncthreads();

    if (threadIdx.x == 0) {
        float b = 0.0f;
#pragma unroll
        for (int i = 0; i < FL_WPB; i++) b += smem[i];

        atomicAdd(&g_fl_scratch, b);
        __threadfence();
        unsigned ticket = atomicAdd(&g_fl_ticket, 1u);
        if (ticket == (unsigned)gridDim.x - 1u) {
            // Last block: all prior scratch-adds are visible (each block's
            // fence ordered its scratch-add before its ticket-add).
            out[0] = g_fl_scratch;
            g_fl_scratch = 0.0f;    // reset for next graph replay
            g_fl_ticket  = 0u;
        }
    }
}

extern "C" void kernel_launch(void* const* d_in, const int* in_sizes, int n_in,
                              void* d_out, int out_size)
{
    const float* x   = (const float*)d_in[0];
    const int*   tgt = (const int*)d_in[1];
    float*       out = (float*)d_out;

    const int n_rows = in_sizes[1];          // 262144 targets
    const float inv_n = 1.0f / (float)n_rows;

    const int blocks = (n_rows + FL_WPB - 1) / FL_WPB;
    focal_loss_kernel<<<blocks, FL_TPB>>>(x, tgt, out, n_rows, inv_n);
}